// round 5
// baseline (speedup 1.0000x reference)
#include <cuda_runtime.h>

#define S_LEN   2048
#define E_DIM   1024
#define NHEADS  16
#define HD      64
#define MAXR    2049   // ns rows + 1 virtual row (xsum -> vtot)
#define KSPLIT  16     // proj K-splits (64 k each)
#define RCAP    128    // rows covered by the split partial-buffer path
#define XS      32     // colsum row splits

// ---------------- device scratch (static, no runtime allocation) ----------------
__device__ int   g_lo, g_ns;
__device__ float g_xsump[XS][E_DIM];
__device__ float g_qp[KSPLIT][RCAP * E_DIM];
__device__ float g_kp[KSPLIT][RCAP * E_DIM];
__device__ float g_vp[KSPLIT][RCAP * E_DIM];
__device__ float g_q[MAXR * E_DIM];
__device__ float g_k[MAXR * E_DIM];
__device__ float g_v[MAXR * E_DIM];   // row ns = vtot
__device__ float g_c[NHEADS * S_LEN]; // per-head softmax column sums
__device__ float g_w0[NHEADS];

// ---------------- f32x2 packed helpers ----------------
__device__ __forceinline__ unsigned long long pk2(float lo, float hi) {
    unsigned long long r;
    asm("mov.b64 %0, {%1,%2};" : "=l"(r) : "f"(lo), "f"(hi));
    return r;
}
__device__ __forceinline__ void upk2(unsigned long long v, float& lo, float& hi) {
    asm("mov.b64 {%0,%1}, %2;" : "=f"(lo), "=f"(hi) : "l"(v));
}
__device__ __forceinline__ void ffma2(unsigned long long& d, unsigned long long a,
                                      unsigned long long b) {
    asm("fma.rn.f32x2 %0, %1, %2, %0;" : "+l"(d) : "l"(a), "l"(b));
}

// ---------------- K0: colsum partials + bounds + zero scratch ----------------
// grid (4, XS), 256 threads
__global__ void __launch_bounds__(256) k_pre(const float* __restrict__ x,
                                             const int* __restrict__ seg,
                                             const int* __restrict__ pos,
                                             float* __restrict__ dout) {
    int bx = blockIdx.x, by = blockIdx.y;
    int tid = threadIdx.x;
    // column-sum partial (rows by*64 .. +63)
    int c  = bx * 256 + tid;
    int r0 = by * (S_LEN / XS);
    float a = 0.f;
#pragma unroll 8
    for (int r = r0; r < r0 + S_LEN / XS; ++r) a += x[(size_t)r * E_DIM + c];
    g_xsump[by][c] = a;
    // zero g_c (grid covers exactly NHEADS*S_LEN = 32768)
    int lb = by * 4 + bx;
    g_c[lb * 256 + tid] = 0.f;
    if (by == 0) dout[bx * 256 + tid] = 0.f;
    if (lb == 0 && tid < NHEADS) g_w0[tid] = 0.f;
    if (lb == 0) {
        __shared__ int s_lo, s_cnt, s_t;
        if (tid == 0) { s_t = seg[pos[0]]; s_lo = 0; s_cnt = 0; }
        __syncthreads();
        int t = s_t, lo = 0, cnt = 0;
        for (int i = tid; i < S_LEN; i += 256) {
            int v = seg[i];
            lo  += (v <  t);
            cnt += (v == t);
        }
        atomicAdd(&s_lo, lo);
        atomicAdd(&s_cnt, cnt);
        __syncthreads();
        if (tid == 0) { g_lo = s_lo; g_ns = s_cnt; }
    }
}

// ---------------- proj tile worker (M = 16*R, N = 128, 16-wide K chunks) ----------------
template<int R>
__device__ __forceinline__ void proj_tile(
    const float* __restrict__ x, const float* __restrict__ W,
    const float* __restrict__ bias, float* __restrict__ outp,
    int lo, int ns, int nrows, int mat, int rowbase, int kbase, int nchunk,
    bool addBias, float (*As)[128], float (*Bs)[128], int colbase)
{
    int tid = threadIdx.x;
    int tx = tid & 15, ty = tid >> 4;
    int arow = (R == 4) ? (tid >> 2) : (tid >> 1);
    int aks  = (R == 4) ? ((tid & 3) << 2) : ((tid & 1) << 3);
    int gr_a = rowbase + arow;
    int bkr = ty, bcol = tx * 8;

    auto ldA = [&](int kidx) -> float4 {
        if (gr_a < ns) return *(const float4*)&x[(size_t)(lo + gr_a) * E_DIM + kidx];
        if (gr_a == ns && mat == 2) {
            float4 s = make_float4(0.f, 0.f, 0.f, 0.f);
#pragma unroll
            for (int p = 0; p < XS; p++) {
                float4 t = *(const float4*)&g_xsump[p][kidx];
                s.x += t.x; s.y += t.y; s.z += t.z; s.w += t.w;
            }
            return s;
        }
        return make_float4(0.f, 0.f, 0.f, 0.f);
    };

    unsigned long long acc[R][4];
#pragma unroll
    for (int r = 0; r < R; r++)
#pragma unroll
        for (int p = 0; p < 4; p++) acc[r][p] = 0ULL;

    float4 a0, a1, b0, b1;
    {   // prefetch chunk 0
        int kidx = kbase + aks;
        a0 = ldA(kidx);
        if (R == 8) a1 = ldA(kidx + 4);
        const float* wp = &W[(size_t)(kbase + bkr) * E_DIM + colbase + bcol];
        b0 = *(const float4*)wp;
        b1 = *(const float4*)(wp + 4);
    }

    for (int c = 0; c < nchunk; c++) {
        As[aks + 0][arow] = a0.x; As[aks + 1][arow] = a0.y;
        As[aks + 2][arow] = a0.z; As[aks + 3][arow] = a0.w;
        if (R == 8) {
            As[aks + 4][arow] = a1.x; As[aks + 5][arow] = a1.y;
            As[aks + 6][arow] = a1.z; As[aks + 7][arow] = a1.w;
        }
        *(float4*)&Bs[bkr][bcol]     = b0;
        *(float4*)&Bs[bkr][bcol + 4] = b1;
        __syncthreads();
        if (c + 1 < nchunk) {
            int kidx = kbase + (c + 1) * 16 + aks;
            a0 = ldA(kidx);
            if (R == 8) a1 = ldA(kidx + 4);
            const float* wp = &W[(size_t)(kbase + (c + 1) * 16 + bkr) * E_DIM + colbase + bcol];
            b0 = *(const float4*)wp;
            b1 = *(const float4*)(wp + 4);
        }
#pragma unroll
        for (int kk = 0; kk < 16; kk++) {
            // B pairs loaded directly as packed f32x2 (adjacent columns, LDS.64)
            unsigned long long bp[4];
#pragma unroll
            for (int p = 0; p < 4; p++)
                bp[p] = *(const unsigned long long*)&Bs[kk][2 * tx + 32 * p];
#pragma unroll
            for (int q = 0; q < R / 4; q++) {
                float4 av = *(float4*)&As[kk][ty * R + 4 * q];
#pragma unroll
                for (int rr = 0; rr < 4; rr++) {
                    float av_s = (rr == 0) ? av.x : (rr == 1) ? av.y : (rr == 2) ? av.z : av.w;
                    unsigned long long ap = pk2(av_s, av_s);
#pragma unroll
                    for (int p = 0; p < 4; p++) ffma2(acc[4 * q + rr][p], ap, bp[p]);
                }
            }
        }
        __syncthreads();
    }
    // epilogue: adjacent-column pairs -> STG.64
#pragma unroll
    for (int r = 0; r < R; r++) {
        int gr = rowbase + ty * R + r;
        if (gr >= nrows) continue;
        bool virt = (gr == ns && mat == 2);
#pragma unroll
        for (int p = 0; p < 4; p++) {
            float v0, v1;
            upk2(acc[r][p], v0, v1);
            int c0 = colbase + 2 * tx + 32 * p;
            if (addBias) {
                float sc = virt ? (float)S_LEN : 1.f;
                v0 += sc * bias[c0];
                v1 += sc * bias[c0 + 1];
            }
            float2 st; st.x = v0; st.y = v1;
            *(float2*)&outp[(size_t)gr * E_DIM + c0] = st;
        }
    }
}

// ---------------- K2: projections (split-K into partial buffers) ----------------
__global__ void __launch_bounds__(256) k_proj(
    const float* __restrict__ x,
    const float* __restrict__ W0, const float* __restrict__ W1,
    const float* __restrict__ W2,
    const float* __restrict__ b0, const float* __restrict__ b1,
    const float* __restrict__ b2) {
    __shared__ __align__(16) float As[16][128];
    __shared__ __align__(16) float Bs[16][128];
    int mat = blockIdx.z;
    int kb  = blockIdx.y;
    int ns = g_ns, lo = g_lo;
    int nrows = ns + (mat == 2 ? 1 : 0);
    const float* W    = (mat == 0) ? W0 : ((mat == 1) ? W1 : W2);
    const float* bias = (mat == 0) ? b0 : ((mat == 1) ? b1 : b2);
    float* partial = (mat == 0) ? g_qp[kb] : ((mat == 1) ? g_kp[kb] : g_vp[kb]);
    float* dense   = (mat == 0) ? g_q : ((mat == 1) ? g_k : g_v);
    int colbase = blockIdx.x * 128;

    int rows_split = min(nrows, RCAP);
    if (rows_split <= 64)
        proj_tile<4>(x, W, bias, partial, lo, ns, rows_split, mat,
                     0, kb * 64, 4, kb == 0, As, Bs, colbase);
    else
        proj_tile<8>(x, W, bias, partial, lo, ns, rows_split, mat,
                     0, kb * 64, 4, kb == 0, As, Bs, colbase);

    // rare overflow: rows >= RCAP computed dense (full K) by kb==0 blocks
    if (nrows > RCAP && kb == 0)
        for (int rowbase = RCAP; rowbase < nrows; rowbase += 64)
            proj_tile<4>(x, W, bias, dense, lo, ns, nrows, mat,
                         rowbase, 0, 64, true, As, Bs, colbase);
}

// ---------------- K2b: sum split-K partials (float4, high MLP) ----------------
// grid (RCAP, 3), 256 threads; each thread sums one float4 across 16 splits
__global__ void __launch_bounds__(256) k_reduce() {
    int ns = g_ns;
    int total = min(ns + 1, RCAP) * E_DIM;
    int base = blockIdx.x * 1024 + threadIdx.x * 4;
    if (base >= total) return;
    int arr = blockIdx.y;
    const float* src = (arr == 0) ? &g_qp[0][0] : ((arr == 1) ? &g_kp[0][0] : &g_vp[0][0]);
    float* dst = (arr == 0) ? g_q : ((arr == 1) ? g_k : g_v);
    float4 s = make_float4(0.f, 0.f, 0.f, 0.f);
#pragma unroll
    for (int p = 0; p < KSPLIT; p++) {
        float4 t = *(const float4*)&src[(size_t)p * (RCAP * E_DIM) + base];
        s.x += t.x; s.y += t.y; s.z += t.z; s.w += t.w;
    }
    *(float4*)&dst[base] = s;
}

// ---------------- K3: per-head softmax column sums ----------------
// grid (NHEADS, 4), 512 threads (16 warps, warp per row)
__global__ void __launch_bounds__(512) k_attn() {
    const int JT = 128;
    int h = blockIdx.x, rb = blockIdx.y, ns = g_ns;
    int tid = threadIdx.x, w = tid >> 5, lane = tid & 31;
    const float* qh = g_q + h * HD;
    const float* kh = g_k + h * HD;

    __shared__ float kbuf[JT][65];
    __shared__ float qr[16][64];
    __shared__ int s_loaded;
    if (tid == 0) s_loaded = -1;
    __syncthreads();

    int nchunks = (ns + JT - 1) / JT;
    int ngroups = (ns + 63) / 64;
    int zc = S_LEN - ns;
    bool cacheS = (ns <= 256);

    for (int g = 0; g < ngroups; ++g) {
        int i = g * 64 + rb * 16 + w;
        bool active = (i < ns);
        if (active) {
            qr[w][lane]      = qh[(size_t)i * E_DIM + lane];
            qr[w][lane + 32] = qh[(size_t)i * E_DIM + lane + 32];
            __syncwarp();
        }
        float sreg[8];
        float m = -1e30f, Z = 0.f;
        for (int c = 0; c < nchunks; c++) {
            int c0 = c * JT;
            int cl = min(JT, ns - c0);
            if (s_loaded != c) {
                __syncthreads();
                for (int idx = tid; idx < cl * HD; idx += 512)
                    kbuf[idx >> 6][idx & 63] =
                        kh[(size_t)(c0 + (idx >> 6)) * E_DIM + (idx & 63)];
                if (tid == 0) s_loaded = c;
                __syncthreads();
            }
            if (active) {
                for (int j = lane; j < cl; j += 32) {
                    float s0 = 0, s1 = 0, s2 = 0, s3 = 0;
#pragma unroll
                    for (int dd = 0; dd < 64; dd += 4) {
                        s0 += qr[w][dd]     * kbuf[j][dd];
                        s1 += qr[w][dd + 1] * kbuf[j][dd + 1];
                        s2 += qr[w][dd + 2] * kbuf[j][dd + 2];
                        s3 += qr[w][dd + 3] * kbuf[j][dd + 3];
                    }
                    float s = (s0 + s1) + (s2 + s3);
                    if (cacheS) sreg[(c0 + j) >> 5] = s;
                    float mn = fmaxf(m, s);
                    Z = Z * __expf(m - mn) + __expf(s - mn);
                    m = mn;
                }
            }
        }
        float mrow = 0.f, invZ = 0.f;
        if (active) {
            mrow = m;
#pragma unroll
            for (int o = 16; o > 0; o >>= 1)
                mrow = fmaxf(mrow, __shfl_xor_sync(0xffffffffu, mrow, o));
            if (zc > 0) mrow = fmaxf(mrow, 0.f);     // masked entries are ZERO, not -inf
            float z = Z * __expf(m - mrow);
#pragma unroll
            for (int o = 16; o > 0; o >>= 1)
                z += __shfl_xor_sync(0xffffffffu, z, o);
            z += (float)zc * __expf(-mrow);
            invZ = 1.f / z;
        }
        if (cacheS) {
            if (active) {
                for (int t = 0; t * 32 < ns; t++) {
                    int jc = t * 32 + lane;
                    if (jc < ns)
                        atomicAdd(&g_c[h * S_LEN + jc], __expf(sreg[t] - mrow) * invZ);
                }
            }
        } else {
            for (int c = 0; c < nchunks; c++) {
                int c0 = c * JT;
                int cl = min(JT, ns - c0);
                if (s_loaded != c) {
                    __syncthreads();
                    for (int idx = tid; idx < cl * HD; idx += 512)
                        kbuf[idx >> 6][idx & 63] =
                            kh[(size_t)(c0 + (idx >> 6)) * E_DIM + (idx & 63)];
                    if (tid == 0) s_loaded = c;
                    __syncthreads();
                }
                if (active) {
                    for (int j = lane; j < cl; j += 32) {
                        float s0 = 0, s1 = 0, s2 = 0, s3 = 0;
#pragma unroll
                        for (int dd = 0; dd < 64; dd += 4) {
                            s0 += qr[w][dd]     * kbuf[j][dd];
                            s1 += qr[w][dd + 1] * kbuf[j][dd + 1];
                            s2 += qr[w][dd + 2] * kbuf[j][dd + 2];
                            s3 += qr[w][dd + 3] * kbuf[j][dd + 3];
                        }
                        float s = (s0 + s1) + (s2 + s3);
                        atomicAdd(&g_c[h * S_LEN + c0 + j], __expf(s - mrow) * invZ);
                    }
                }
            }
        }
        if (active && lane == 0) atomicAdd(&g_w0[h], __expf(-mrow) * invZ);
    }
}

// ---------------- K4: att slice + final vecmat ----------------
// grid (4 coltiles, 8 kslices of 128), 256 threads
__global__ void __launch_bounds__(256) k_out(const float* __restrict__ Wo,
                                             const float* __restrict__ bo,
                                             float* __restrict__ dout) {
    int ky = blockIdx.y;
    int k0 = ky * 128;
    int h0 = ky * 2;
    int ns = g_ns;
    int tid = threadIdx.x;

    __shared__ float att_s[128];
    __shared__ float c_s[2][S_LEN];
    __shared__ float w0s[2];

    if (tid < 2) w0s[tid] = g_w0[h0 + tid];
    for (int i = tid; i < ns; i += 256) {
        c_s[0][i] = g_c[h0 * S_LEN + i];
        c_s[1][i] = g_c[(h0 + 1) * S_LEN + i];
    }
    __syncthreads();

    if (tid < 128) {
        int d = tid;
        int hl = d >> 6;
        float w0 = w0s[hl];
        const float* cp = c_s[hl];
        float a0 = 0.f, a1 = 0.f, a2 = 0.f, a3 = 0.f;
        int j = 0;
        for (; j + 4 <= ns; j += 4) {
            a0 += (cp[j]     - w0) * g_v[(size_t)(j)     * E_DIM + k0 + d];
            a1 += (cp[j + 1] - w0) * g_v[(size_t)(j + 1) * E_DIM + k0 + d];
            a2 += (cp[j + 2] - w0) * g_v[(size_t)(j + 2) * E_DIM + k0 + d];
            a3 += (cp[j + 3] - w0) * g_v[(size_t)(j + 3) * E_DIM + k0 + d];
        }
        for (; j < ns; j++)
            a0 += (cp[j] - w0) * g_v[(size_t)j * E_DIM + k0 + d];
        float acc = (a0 + a1) + (a2 + a3);
        acc += w0 * g_v[(size_t)ns * E_DIM + k0 + d];   // vtot row
        att_s[d] = acc / (float)ns;
    }
    __syncthreads();

    int c = blockIdx.x * 256 + tid;
    float acc = (ky == 0) ? bo[c] : 0.f;
#pragma unroll 8
    for (int kk = 0; kk < 128; kk++)
        acc += att_s[kk] * Wo[(size_t)(k0 + kk) * E_DIM + c];
    atomicAdd(&dout[c], acc);
}

// ---------------- launch ----------------
extern "C" void kernel_launch(void* const* d_in, const int* in_sizes, int n_in,
                              void* d_out, int out_size) {
    const float* x   = (const float*)d_in[0];
    const int*   seg = (const int*)d_in[1];
    const int*   pos = (const int*)d_in[2];
    const float* Wq = (const float*)d_in[3];
    const float* bq = (const float*)d_in[4];
    const float* Wk = (const float*)d_in[5];
    const float* bk = (const float*)d_in[6];
    const float* Wv = (const float*)d_in[7];
    const float* bv = (const float*)d_in[8];
    const float* Wo = (const float*)d_in[9];
    const float* bo = (const float*)d_in[10];
    float* out = (float*)d_out;

    k_pre<<<dim3(4, XS), 256>>>(x, seg, pos, out);
    k_proj<<<dim3(8, KSPLIT, 3), 256>>>(x, Wq, Wk, Wv, bq, bk, bv);
    k_reduce<<<dim3(RCAP, 3), 256>>>();
    k_attn<<<dim3(NHEADS, 4), 512>>>();
    k_out<<<dim3(4, 8), 256>>>(Wo, bo, out);
}